// round 6
// baseline (speedup 1.0000x reference)
#include <cuda_runtime.h>
#include <stdint.h>

// ---------------- problem constants ----------------
#define BATCH     16
#define KTOP      5000
#define NBINS     4096          // top-12-bit monotonic-float bins
#define CAND_CAP  8192
#define BK        (BATCH*KTOP)  // 80000

// supertile = 512 elements (per warp-iteration, 4 float4 loads/lane)
// subgroup  = 32 elements (gmax granularity)
#define ST_PB   8633            // supertiles/batch: 6480+1620+405+102+26
#define NSG     (ST_PB*16)      // 138128 subgroups per batch

// ---------------- scratch (no allocation; reset by k_emit each run) ----------------
static __device__ unsigned int        d_ghist[BATCH * NBINS];       // zero-init
static __device__ unsigned int        d_candcnt[BATCH];             // zero-init
static __device__ unsigned int        d_gmax32[BATCH * ST_PB * 8];  // fully rewritten by scan
static __device__ unsigned long long  d_cand[BATCH * CAND_CAP];     // fully rewritten by sort1
static __device__ unsigned long long  d_cand2[BATCH * CAND_CAP];    // merge ping-pong

__device__ __forceinline__ unsigned int ordu(float f) {
    unsigned int u = __float_as_uint(f);
    return (u & 0x80000000u) ? ~u : (u | 0x80000000u);
}

// ---------------- pass 1: stream cls, subgroup maxima (NO atomics) ----------------
__global__ __launch_bounds__(1024, 2) void k_scan(
    const float* __restrict__ c0, const float* __restrict__ c1,
    const float* __restrict__ c2, const float* __restrict__ c3,
    const float* __restrict__ c4)
{
    int b    = blockIdx.y;
    int warp = threadIdx.x >> 5;
    int lane = threadIdx.x & 31;
    for (int st = blockIdx.x * 32 + warp; st < ST_PB; st += gridDim.x * 32) {
        const float* cp; int E, stl;
        if (st < 6480)      { cp = c0; E = 3317760; stl = st;        }
        else if (st < 8100) { cp = c1; E = 829440;  stl = st - 6480; }
        else if (st < 8505) { cp = c2; E = 207360;  stl = st - 8100; }
        else if (st < 8607) { cp = c3; E = 51840;   stl = st - 8505; }
        else                { cp = c4; E = 12960;   stl = st - 8607; }
        const float* p = cp + (size_t)b * E;
        int m0 = stl * 512 + lane * 4;
        unsigned int q[4];
        #pragma unroll
        for (int c = 0; c < 4; c++) {
            int off = m0 + c * 128;
            unsigned int m = 0u;
            if (off < E) {                  // E%4==0 -> whole float4 valid
                float4 v = *(const float4*)(p + off);
                m = max(max(ordu(v.x), ordu(v.y)), max(ordu(v.z), ordu(v.w))) >> 20;
            }
            q[c] = m;
        }
        unsigned int pk0 = (q[1] << 16) | q[0];
        unsigned int pk1 = (q[3] << 16) | q[2];
        #pragma unroll
        for (int o = 1; o <= 4; o <<= 1) {
            pk0 = __vmaxu2(pk0, __shfl_xor_sync(0xffffffffu, pk0, o));
            pk1 = __vmaxu2(pk1, __shfl_xor_sync(0xffffffffu, pk1, o));
        }
        if ((lane & 7) == 0) {              // octet leaders: lanes 0,8,16,24
            size_t idx = ((size_t)b * ST_PB + st) * 8 + (lane >> 3) * 2;
            d_gmax32[idx]     = pk0;
            d_gmax32[idx + 1] = pk1;
        }
    }
}

// ---------------- pass 1b: histogram of subgroup maxima (small, isolated) ----------------
__global__ __launch_bounds__(256) void k_hist() {
    __shared__ unsigned int sh[NBINS];
    int b = blockIdx.y, slice = blockIdx.x;      // (8, BATCH)
    for (int i = threadIdx.x; i < NBINS; i += 256) sh[i] = 0u;
    __syncthreads();
    const unsigned int* gm = d_gmax32 + (size_t)b * ST_PB * 8 + slice * 8633;
    for (int i = threadIdx.x; i < 8633; i += 256) {
        unsigned int v = gm[i];
        atomicAdd(&sh[v & 0xffffu], 1u);
        atomicAdd(&sh[v >> 16], 1u);
    }
    __syncthreads();
    for (int i = threadIdx.x; i < NBINS; i += 256) {
        unsigned int c = sh[i];
        if (c) atomicAdd(&d_ghist[b * NBINS + i], c);
    }
}

// ---------------- pass 2: inline-threshold + compact candidates ----------------
__global__ __launch_bounds__(1024, 2) void k_compact(
    const float* __restrict__ c0, const float* __restrict__ c1,
    const float* __restrict__ c2, const float* __restrict__ c3,
    const float* __restrict__ c4)
{
    __shared__ unsigned int ss[1024];
    __shared__ unsigned int s_thr;
    int b = blockIdx.y;
    int t = threadIdx.x;
    // --- compute threshold from global histogram (every block, deterministic) ---
    const unsigned int* h = d_ghist + b * NBINS;
    unsigned int h0 = h[4*t], h1 = h[4*t+1], h2 = h[4*t+2], h3 = h[4*t+3];
    unsigned int s = h0 + h1 + h2 + h3;
    ss[t] = s;
    for (int off = 1; off < 1024; off <<= 1) {
        __syncthreads();
        unsigned int add = (t + off < 1024) ? ss[t + off] : 0u;
        __syncthreads();
        ss[t] += add;
    }
    __syncthreads();
    unsigned int suf_excl = ss[t] - s;               // strictly-higher chunks
    if (suf_excl < (unsigned)KTOP && suf_excl + s >= (unsigned)KTOP) {
        unsigned int acc = suf_excl + h3;
        unsigned int tb = 4*t + 3;
        if (acc < (unsigned)KTOP) { acc += h2; tb = 4*t + 2; }
        if (acc < (unsigned)KTOP) { acc += h1; tb = 4*t + 1; }
        if (acc < (unsigned)KTOP) {            tb = 4*t;     }
        s_thr = tb;
    }
    __syncthreads();
    unsigned int thr = s_thr;

    // --- compact: revisit only hot 32-elem subgroups ---
    int warp = t >> 5, lane = t & 31;
    const unsigned short* gm = (const unsigned short*)d_gmax32 + (size_t)b * NSG;
    for (int base = (blockIdx.x * 32 + warp) * 32; base < NSG;
         base += gridDim.x * 32 * 32) {
        int i = base + lane;
        unsigned int g = (i < NSG) ? gm[i] : 0u;
        unsigned int mask = __ballot_sync(0xffffffffu, g >= thr);
        while (mask) {
            int sft = __ffs(mask) - 1; mask &= mask - 1;
            int sg = base + sft;
            int st = sg >> 4, o = (sg >> 2) & 3, c = sg & 3;
            const float* cp; int E, stl, s2sh; unsigned int goff;
            if (st < 6480)      { cp = c0; E = 3317760; stl = st;        s2sh = 12; goff = 0u;       }
            else if (st < 8100) { cp = c1; E = 829440;  stl = st - 6480; s2sh = 10; goff = 3317760u; }
            else if (st < 8505) { cp = c2; E = 207360;  stl = st - 8100; s2sh = 8;  goff = 4147200u; }
            else if (st < 8607) { cp = c3; E = 51840;   stl = st - 8505; s2sh = 6;  goff = 4354560u; }
            else                { cp = c4; E = 12960;   stl = st - 8607; s2sh = 4;  goff = 4406400u; }
            int m = stl * 512 + c * 128 + o * 32 + lane;   // subgroup fully valid (E%32==0)
            unsigned int ou = ordu(cp[(size_t)b * E + m]);
            bool pass = ((ou >> 20) >= thr);
            unsigned int pm = __ballot_sync(0xffffffffu, pass);
            if (pm) {
                int leader = __ffs(pm) - 1;
                unsigned int pos = 0u;
                if (lane == leader) pos = atomicAdd(&d_candcnt[b], (unsigned)__popc(pm));
                pos = __shfl_sync(0xffffffffu, pos, leader);
                if (pass) {
                    unsigned int off = pos + __popc(pm & ((1u << lane) - 1u));
                    if (off < CAND_CAP) {
                        int ch = m >> s2sh;
                        int hw = m & ((1 << s2sh) - 1);
                        unsigned int gidx = goff + (unsigned)hw * 810u + (unsigned)ch;
                        d_cand[b * CAND_CAP + off] =
                            ((unsigned long long)ou << 32) | (unsigned int)(~gidx);
                    }
                }
            }
        }
    }
}

// ---------------- pass 3a: bitonic sort -> DESCENDING 1024-key runs ----------------
__global__ __launch_bounds__(512, 2) void k_sort1() {
    __shared__ unsigned long long sk[1024];
    int seg = blockIdx.x, b = blockIdx.y, t = threadIdx.x;
    unsigned int n = d_candcnt[b];
    if (n > CAND_CAP) n = CAND_CAP;
    unsigned long long* cand = d_cand + (size_t)b * CAND_CAP + seg * 1024;
    int gbase = seg * 1024;
    for (int i = t; i < 1024; i += 512)
        sk[i] = (gbase + i < (int)n) ? cand[i] : 0ull;
    __syncthreads();
    for (unsigned int k = 2; k <= 1024; k <<= 1) {
        for (unsigned int j = k >> 1; j > 0; j >>= 1) {
            for (unsigned int i = t; i < 1024; i += 512) {
                unsigned int ix = i ^ j;
                if (ix > i) {
                    unsigned long long a = sk[i], c = sk[ix];
                    bool desc = ((i & k) == 0);       // LOCAL index -> descending run
                    if ((a < c) == desc) { sk[i] = c; sk[ix] = a; }
                }
            }
            __syncthreads();
        }
    }
    for (int i = t; i < 1024; i += 512) cand[i] = sk[i];
}

// ---------------- pass 3b: merge-path pairwise merge of descending runs ----------------
// dir==0: d_cand -> d_cand2 ; dir==1: d_cand2 -> d_cand. Runs of length n -> 2n.
__global__ __launch_bounds__(256) void k_merge(int n, int dir) {
    const int T = 8;
    int tid = blockIdx.x * 256 + threadIdx.x;        // BATCH * CAND_CAP / T = 16384
    int b = tid / (CAND_CAP / T);
    int r = tid % (CAND_CAP / T);
    int tpp = (2 * n) / T;                           // threads per pair
    int pair = r / tpp;
    int d0 = (r % tpp) * T;
    const unsigned long long* src = (dir == 0 ? d_cand : d_cand2)
                                    + (size_t)b * CAND_CAP + pair * 2 * n;
    unsigned long long* dst = (dir == 0 ? d_cand2 : d_cand)
                              + (size_t)b * CAND_CAP + pair * 2 * n;
    const unsigned long long* A = src;
    const unsigned long long* B = src + n;
    int lo = d0 > n ? d0 - n : 0;
    int hi = d0 < n ? d0 : n;
    while (lo < hi) {
        int mid = (lo + hi) >> 1;
        if (A[mid] > B[d0 - 1 - mid]) lo = mid + 1; else hi = mid;
    }
    int ai = lo, bi = d0 - lo;
    #pragma unroll
    for (int t = 0; t < T; t++) {
        bool takeA = (bi >= n) || (ai < n && A[ai] > B[bi]);
        dst[d0 + t] = takeA ? A[ai++] : B[bi++];
    }
}

// ---------------- pass 4: decode + box gather + emit + scratch reset ----------------
__global__ __launch_bounds__(256) void k_emit(
    const float* __restrict__ b0, const float* __restrict__ b1,
    const float* __restrict__ b2, const float* __restrict__ b3,
    const float* __restrict__ b4, float* __restrict__ out)
{
    int b = blockIdx.y;
    int kk = blockIdx.x * 256 + threadIdx.x;
    // reset scratch for the next graph replay (deterministic across replays)
    if (kk < NBINS) d_ghist[b * NBINS + kk] = 0u;
    if (kk == 0)    d_candcnt[b] = 0u;
    if (kk >= KTOP) return;
    unsigned long long key = d_cand2[(size_t)b * CAND_CAP + kk];   // final merge output
    unsigned int o = (unsigned int)(key >> 32);
    unsigned int g = ~((unsigned int)key);
    unsigned int bits = (o & 0x80000000u) ? (o & 0x7fffffffu) : ~o;
    float val = __uint_as_float(bits);
    unsigned int anchor = g / 90u;
    unsigned int cls = g - anchor * 90u;
    const float* bp; unsigned int aoff, S2;
    if (anchor < 36864u)      { bp = b0; aoff = 0u;     S2 = 4096u; }
    else if (anchor < 46080u) { bp = b1; aoff = 36864u; S2 = 1024u; }
    else if (anchor < 48384u) { bp = b2; aoff = 46080u; S2 = 256u;  }
    else if (anchor < 48960u) { bp = b3; aoff = 48384u; S2 = 64u;   }
    else                      { bp = b4; aoff = 48960u; S2 = 16u;   }
    unsigned int la = anchor - aoff;
    unsigned int hw = la / 9u;
    unsigned int a9 = la - hw * 9u;
    size_t base = (size_t)b * 36 * S2 + (size_t)a9 * 4 * S2 + hw;
    int ok = b * KTOP + kk;
    out[ok] = val;                                   // cls_topk  [B,K,1]
    out[BK + 4*ok + 0] = bp[base];                   // box_topk  [B,K,4]
    out[BK + 4*ok + 1] = bp[base +     S2];
    out[BK + 4*ok + 2] = bp[base + 2 * S2];
    out[BK + 4*ok + 3] = bp[base + 3 * S2];
    out[BK * 5 + ok] = (float)anchor;                // indices   [B,K]
    out[BK * 6 + ok] = (float)cls;                   // classes   [B,K]
}

// ---------------- launcher (8 graph nodes) ----------------
extern "C" void kernel_launch(void* const* d_in, const int* in_sizes, int n_in,
                              void* d_out, int out_size)
{
    (void)out_size;
    static const int csz[5] = {53084160, 13271040, 3317760, 829440, 207360};
    static const int bsz[5] = {2359296,  589824,   147456,  36864,  9216};
    const float* cls[5] = {0,0,0,0,0};
    const float* box[5] = {0,0,0,0,0};
    for (int i = 0; i < n_in; i++) {
        for (int l = 0; l < 5; l++) {
            if (in_sizes[i] == csz[l]) cls[l] = (const float*)d_in[i];
            if (in_sizes[i] == bsz[l]) box[l] = (const float*)d_in[i];
        }
    }

    dim3 gs(18, BATCH);
    k_scan<<<gs, 1024>>>(cls[0], cls[1], cls[2], cls[3], cls[4]);
    k_hist<<<dim3(8, BATCH), 256>>>();
    k_compact<<<gs, 1024>>>(cls[0], cls[1], cls[2], cls[3], cls[4]);

    k_sort1<<<dim3(8, BATCH), 512>>>();              // descending 1024-runs
    k_merge<<<64, 256>>>(1024, 0);                   // 1024 -> 2048  (cand -> cand2)
    k_merge<<<64, 256>>>(2048, 1);                   // 2048 -> 4096  (cand2 -> cand)
    k_merge<<<64, 256>>>(4096, 0);                   // 4096 -> 8192  (cand -> cand2)

    k_emit<<<dim3((KTOP + 255) / 256, BATCH), 256>>>(
        box[0], box[1], box[2], box[3], box[4], (float*)d_out);
}